// round 10
// baseline (speedup 1.0000x reference)
#include <cuda_runtime.h>

#define NB 32
#define NS 4096
#define ND 1024
#define NEGV -1e37f

#define SCHUNK 128
#define NCH (NS / SCHUNK)   // 32
#define QKB (NS / 8)        // 512 qk blocks per batch

// scratch: logits then softmax weights [B, S]
__device__ float g_logits[NB * NS];
// partial PV sums [B, NCH, D]
__device__ float g_part[NB * NCH * ND];
// per-batch completion counters (zero-init; reset by tail blocks each run)
__device__ int g_cnt1[NB];
__device__ int g_cnt2[NB];

// ---------------------------------------------------------------------------
// Kernel 1: logits[b,s] = q[b] . k[b,s]; the LAST block per batch (completion
// counter) runs the batch softmax inline on L2-hot logits.
// 256 threads = 8 warps, each warp one s-row; q[b] staged in shared.
// Mask is int32 (JAX bool widened): nonzero = valid.
// ---------------------------------------------------------------------------
__global__ __launch_bounds__(256) void qk_kernel(
    const float* __restrict__ keys,
    const float* __restrict__ queries,
    const int* __restrict__ mask)
{
    int b  = blockIdx.x / QKB;
    int s0 = (blockIdx.x % QKB) * 8;

    __shared__ float4 qs[ND / 4];
    __shared__ float  red[8];
    __shared__ int    lastflag;

    int t = threadIdx.x;
    qs[t] = ((const float4*)(queries + (size_t)b * ND))[t];
    __syncthreads();

    int warp = t >> 5;
    int lane = t & 31;
    int s = s0 + warp;

    bool valid = mask[b * NS + s] != 0;
    float acc = 0.f;
    if (valid) {
        const float4* k4 = (const float4*)(keys + ((size_t)b * NS + s) * ND);
#pragma unroll
        for (int i = 0; i < 8; i++) {
            int idx = i * 32 + lane;          // 0..255 float4s
            float4 kv = k4[idx];
            float4 qv = qs[idx];
            acc += kv.x * qv.x + kv.y * qv.y + kv.z * qv.z + kv.w * qv.w;
        }
#pragma unroll
        for (int o = 16; o; o >>= 1)
            acc += __shfl_xor_sync(0xFFFFFFFFu, acc, o);
    }
    if (lane == 0) g_logits[b * NS + s] = valid ? acc : NEGV;

    // ---- completion counter: last block of batch b does the softmax -------
    __syncthreads();
    if (t == 0) {
        __threadfence();
        lastflag = (atomicAdd(&g_cnt1[b], 1) == QKB - 1);
    }
    __syncthreads();
    if (!lastflag) return;
    __threadfence();   // acquire: see all blocks' logits

    float* row = g_logits + b * NS;
    float v[16];
#pragma unroll
    for (int j = 0; j < 16; j++) v[j] = row[t + 256 * j];

    // block max
    float m = v[0];
#pragma unroll
    for (int j = 1; j < 16; j++) m = fmaxf(m, v[j]);
#pragma unroll
    for (int o = 16; o; o >>= 1) m = fmaxf(m, __shfl_xor_sync(0xFFFFFFFFu, m, o));
    if (lane == 0) red[warp] = m;
    __syncthreads();
    if (t < 32) {
        float x = (lane < 8) ? red[lane] : NEGV;
#pragma unroll
        for (int o = 4; o; o >>= 1) x = fmaxf(x, __shfl_xor_sync(0xFFFFFFFFu, x, o));
        if (lane == 0) red[0] = x;
    }
    __syncthreads();
    m = red[0];
    __syncthreads();

    // exp + block sum
    float s_loc = 0.f;
#pragma unroll
    for (int j = 0; j < 16; j++) { v[j] = __expf(v[j] - m); s_loc += v[j]; }
#pragma unroll
    for (int o = 16; o; o >>= 1) s_loc += __shfl_xor_sync(0xFFFFFFFFu, s_loc, o);
    if (lane == 0) red[warp] = s_loc;
    __syncthreads();
    if (t == 0) {
        float tot = 0.f;
#pragma unroll
        for (int i = 0; i < 8; i++) tot += red[i];
        red[0] = 1.0f / tot;
        g_cnt1[b] = 0;                       // reset for next replay
    }
    __syncthreads();
    float inv = red[0];
#pragma unroll
    for (int j = 0; j < 16; j++) row[t + 256 * j] = v[j] * inv;
}

// ---------------------------------------------------------------------------
// Kernel 2: partial PV. Block = (b, 128-row s-chunk), 1024 blocks total.
// 256 threads, each owns a float4 of D. Skips V rows whose weight is exactly 0.
// The LAST block per batch reduces the 32 partials (fixed order) -> out[b,:].
// ---------------------------------------------------------------------------
__global__ __launch_bounds__(256) void pv_kernel(
    const float* __restrict__ values,
    float* __restrict__ out)
{
    int chunk = blockIdx.x & (NCH - 1);
    int b     = blockIdx.x / NCH;
    int s0    = chunk * SCHUNK;

    __shared__ float ws[SCHUNK];
    __shared__ int   lastflag;
    int t = threadIdx.x;
    if (t < SCHUNK) ws[t] = g_logits[b * NS + s0 + t];
    __syncthreads();

    const float4* v4 = (const float4*)(values + ((size_t)b * NS + s0) * ND);
    float4 acc = make_float4(0.f, 0.f, 0.f, 0.f);

#pragma unroll 4
    for (int i = 0; i < SCHUNK; i += 4) {
        float w0 = ws[i], w1 = ws[i + 1], w2 = ws[i + 2], w3 = ws[i + 3];
        float4 a = make_float4(0.f, 0.f, 0.f, 0.f);
        float4 c = make_float4(0.f, 0.f, 0.f, 0.f);
        float4 d = make_float4(0.f, 0.f, 0.f, 0.f);
        float4 e = make_float4(0.f, 0.f, 0.f, 0.f);
        if (w0 != 0.f) a = v4[(size_t)(i + 0) * (ND / 4) + t];
        if (w1 != 0.f) c = v4[(size_t)(i + 1) * (ND / 4) + t];
        if (w2 != 0.f) d = v4[(size_t)(i + 2) * (ND / 4) + t];
        if (w3 != 0.f) e = v4[(size_t)(i + 3) * (ND / 4) + t];
        acc.x += w0 * a.x; acc.y += w0 * a.y; acc.z += w0 * a.z; acc.w += w0 * a.w;
        acc.x += w1 * c.x; acc.y += w1 * c.y; acc.z += w1 * c.z; acc.w += w1 * c.w;
        acc.x += w2 * d.x; acc.y += w2 * d.y; acc.z += w2 * d.z; acc.w += w2 * d.w;
        acc.x += w3 * e.x; acc.y += w3 * e.y; acc.z += w3 * e.z; acc.w += w3 * e.w;
    }

    ((float4*)g_part)[(size_t)(b * NCH + chunk) * (ND / 4) + t] = acc;

    // ---- completion counter: last block of batch b reduces its partials ---
    __syncthreads();
    if (t == 0) {
        __threadfence();
        lastflag = (atomicAdd(&g_cnt2[b], 1) == NCH - 1);
    }
    __syncthreads();
    if (!lastflag) return;
    __threadfence();   // acquire: see all blocks' partials

    const float4* p4 = (const float4*)g_part + (size_t)b * NCH * (ND / 4) + t;
    float4 r = make_float4(0.f, 0.f, 0.f, 0.f);
#pragma unroll
    for (int c = 0; c < NCH; c++) {
        float4 vv = p4[(size_t)c * (ND / 4)];
        r.x += vv.x; r.y += vv.y; r.z += vv.z; r.w += vv.w;
    }
    ((float4*)out)[(size_t)b * (ND / 4) + t] = r;

    if (t == 0) g_cnt2[b] = 0;               // reset for next replay
}

// ---------------------------------------------------------------------------
extern "C" void kernel_launch(void* const* d_in, const int* in_sizes, int n_in,
                              void* d_out, int out_size)
{
    const float* keys    = (const float*)d_in[0];
    const float* queries = (const float*)d_in[1];
    const float* values  = (const float*)d_in[2];
    const int*   mask    = (const int*)d_in[3];
    float* out = (float*)d_out;

    qk_kernel<<<NB * QKB, 256>>>(keys, queries, mask);
    pv_kernel<<<NB * NCH, 256>>>(values, out);
}

// round 11
// speedup vs baseline: 1.2627x; 1.2627x over previous
#include <cuda_runtime.h>

#define NB 32
#define NS 4096
#define ND 1024
#define NEGV -1e37f

#define SCHUNK 128
#define NCH (NS / SCHUNK)   // 32

// scratch: logits then softmax weights [B, S]
__device__ float g_logits[NB * NS];
// partial PV sums [B, NCH, D]
__device__ float g_part[NB * NCH * ND];

// ---------------------------------------------------------------------------
// Kernel 1: logits[b,s] = q[b] . k[b,s]  (masked rows: skip K read, write NEG)
// 256 threads = 8 warps, each warp one s-row; q[b] staged in shared.
// K loads use __ldcs (evict-first): zero-reuse stream, keeps logits L2-hot.
// Mask is int32 (JAX bool widened): nonzero = valid.
// ---------------------------------------------------------------------------
__global__ __launch_bounds__(256) void qk_kernel(
    const float* __restrict__ keys,
    const float* __restrict__ queries,
    const int* __restrict__ mask)
{
    const int rows_per_block = 8;
    int b  = blockIdx.x / (NS / rows_per_block);
    int s0 = (blockIdx.x % (NS / rows_per_block)) * rows_per_block;

    __shared__ float4 qs[ND / 4];
    qs[threadIdx.x] = ((const float4*)(queries + (size_t)b * ND))[threadIdx.x];
    __syncthreads();

    int warp = threadIdx.x >> 5;
    int lane = threadIdx.x & 31;
    int s = s0 + warp;

    if (mask[b * NS + s] == 0) {
        if (lane == 0) g_logits[b * NS + s] = NEGV;
        return;
    }

    const float4* k4 = (const float4*)(keys + ((size_t)b * NS + s) * ND);
    float acc = 0.f;
#pragma unroll
    for (int i = 0; i < 8; i++) {
        int idx = i * 32 + lane;          // 0..255 float4s
        float4 kv = __ldcs(&k4[idx]);
        float4 qv = qs[idx];
        acc += kv.x * qv.x + kv.y * qv.y + kv.z * qv.z + kv.w * qv.w;
    }
#pragma unroll
    for (int o = 16; o; o >>= 1)
        acc += __shfl_xor_sync(0xFFFFFFFFu, acc, o);

    if (lane == 0) g_logits[b * NS + s] = acc;
}

// ---------------------------------------------------------------------------
// Kernel 2: per-batch softmax over S=4096. One block of 1024 threads per batch.
// Masked logits (-1e37) underflow to exactly 0.0f after exp.
// ---------------------------------------------------------------------------
__global__ __launch_bounds__(1024) void softmax_kernel()
{
    int b = blockIdx.x;
    int t = threadIdx.x;
    float* row = g_logits + b * NS;

    float v0 = row[t];
    float v1 = row[t + 1024];
    float v2 = row[t + 2048];
    float v3 = row[t + 3072];

    __shared__ float red[32];

    // ---- max reduce ----
    float m = fmaxf(fmaxf(v0, v1), fmaxf(v2, v3));
#pragma unroll
    for (int o = 16; o; o >>= 1) m = fmaxf(m, __shfl_xor_sync(0xFFFFFFFFu, m, o));
    if ((t & 31) == 0) red[t >> 5] = m;
    __syncthreads();
    if (t < 32) {
        float x = red[t];
#pragma unroll
        for (int o = 16; o; o >>= 1) x = fmaxf(x, __shfl_xor_sync(0xFFFFFFFFu, x, o));
        red[t] = x;
    }
    __syncthreads();
    m = red[0];
    __syncthreads();

    // ---- exp + sum reduce ----
    float e0 = __expf(v0 - m);
    float e1 = __expf(v1 - m);
    float e2 = __expf(v2 - m);
    float e3 = __expf(v3 - m);
    float s = e0 + e1 + e2 + e3;
#pragma unroll
    for (int o = 16; o; o >>= 1) s += __shfl_xor_sync(0xFFFFFFFFu, s, o);
    if ((t & 31) == 0) red[t >> 5] = s;
    __syncthreads();
    if (t < 32) {
        float x = red[t];
#pragma unroll
        for (int o = 16; o; o >>= 1) x += __shfl_xor_sync(0xFFFFFFFFu, x, o);
        red[t] = x;
    }
    __syncthreads();
    float inv = 1.0f / red[0];

    row[t]        = e0 * inv;
    row[t + 1024] = e1 * inv;
    row[t + 2048] = e2 * inv;
    row[t + 3072] = e3 * inv;
}

// ---------------------------------------------------------------------------
// Kernel 3: partial PV. Block = (b, 128-row s-chunk), 1024 blocks total.
// 256 threads, each owns a float4 of D. Skips V rows whose weight is exactly 0
// (masked). V loads use __ldcs (evict-first): zero-reuse stream, keeps the
// freshly written g_part partials L2-resident for the reduce kernel.
// ---------------------------------------------------------------------------
__global__ __launch_bounds__(256) void pv_kernel(const float* __restrict__ values)
{
    int chunk = blockIdx.x & (NCH - 1);
    int b     = blockIdx.x / NCH;
    int s0    = chunk * SCHUNK;

    __shared__ float ws[SCHUNK];
    int t = threadIdx.x;
    if (t < SCHUNK) ws[t] = g_logits[b * NS + s0 + t];
    __syncthreads();

    const float4* v4 = (const float4*)(values + ((size_t)b * NS + s0) * ND);
    float4 acc = make_float4(0.f, 0.f, 0.f, 0.f);

#pragma unroll 4
    for (int i = 0; i < SCHUNK; i += 4) {
        float w0 = ws[i], w1 = ws[i + 1], w2 = ws[i + 2], w3 = ws[i + 3];
        float4 a = make_float4(0.f, 0.f, 0.f, 0.f);
        float4 c = make_float4(0.f, 0.f, 0.f, 0.f);
        float4 d = make_float4(0.f, 0.f, 0.f, 0.f);
        float4 e = make_float4(0.f, 0.f, 0.f, 0.f);
        if (w0 != 0.f) a = __ldcs(&v4[(size_t)(i + 0) * (ND / 4) + t]);
        if (w1 != 0.f) c = __ldcs(&v4[(size_t)(i + 1) * (ND / 4) + t]);
        if (w2 != 0.f) d = __ldcs(&v4[(size_t)(i + 2) * (ND / 4) + t]);
        if (w3 != 0.f) e = __ldcs(&v4[(size_t)(i + 3) * (ND / 4) + t]);
        acc.x += w0 * a.x; acc.y += w0 * a.y; acc.z += w0 * a.z; acc.w += w0 * a.w;
        acc.x += w1 * c.x; acc.y += w1 * c.y; acc.z += w1 * c.z; acc.w += w1 * c.w;
        acc.x += w2 * d.x; acc.y += w2 * d.y; acc.z += w2 * d.z; acc.w += w2 * d.w;
        acc.x += w3 * e.x; acc.y += w3 * e.y; acc.z += w3 * e.z; acc.w += w3 * e.w;
    }

    ((float4*)g_part)[(size_t)(b * NCH + chunk) * (ND / 4) + t] = acc;
}

// ---------------------------------------------------------------------------
// Kernel 4: out[b,:] = sum over 32 chunks of g_part[b,c,:].
// 256 blocks x 256 threads; 8 threads cooperate per float4 output
// (4 coalesced chunk-loads each), fixed-order combine via shared memory.
// With __ldcs upstream, g_part should now be read from L2, not DRAM.
// ---------------------------------------------------------------------------
__global__ __launch_bounds__(256) void reduce_kernel(float* __restrict__ out)
{
    int t    = threadIdx.x;
    int oct  = t >> 5;                 // 0..7 chunk-octant
    int slot = t & 31;                 // 0..31 output slot within block
    int o  = blockIdx.x * 32 + slot;   // 0..8191 global float4 output index
    int b  = o >> 8;                   // ND/4 = 256 float4 per batch
    int d4 = o & 255;

    const float4* p4 = (const float4*)g_part + ((size_t)b * NCH) * (ND / 4) + d4;

    float4 acc = make_float4(0.f, 0.f, 0.f, 0.f);
#pragma unroll
    for (int c = 0; c < 4; c++) {
        float4 v = p4[(size_t)(oct * 4 + c) * (ND / 4)];
        acc.x += v.x; acc.y += v.y; acc.z += v.z; acc.w += v.w;
    }

    __shared__ float4 sp[7 * 32];      // octants 1..7
    if (oct > 0) sp[(oct - 1) * 32 + slot] = acc;
    __syncthreads();

    if (oct == 0) {
#pragma unroll
        for (int i = 0; i < 7; i++) {
            float4 v = sp[i * 32 + slot];
            acc.x += v.x; acc.y += v.y; acc.z += v.z; acc.w += v.w;
        }
        ((float4*)out)[o] = acc;
    }
}

// ---------------------------------------------------------------------------
extern "C" void kernel_launch(void* const* d_in, const int* in_sizes, int n_in,
                              void* d_out, int out_size)
{
    const float* keys    = (const float*)d_in[0];
    const float* queries = (const float*)d_in[1];
    const float* values  = (const float*)d_in[2];
    const int*   mask    = (const int*)d_in[3];
    float* out = (float*)d_out;

    qk_kernel<<<NB * (NS / 8), 256>>>(keys, queries, mask);
    softmax_kernel<<<NB, 1024>>>();
    pv_kernel<<<NB * NCH, 256>>>(values);
    reduce_kernel<<<256, 256>>>(out);
}